// round 8
// baseline (speedup 1.0000x reference)
#include <cuda_runtime.h>
#include <cuda_bf16.h>
#include <cstdint>

#define DIM 128
#define N_NODES_MAX 50000
#define N_EDGES_MAX 640000
#define TILE_M 64
#define THREADS 512
#define SA 136   // bf16-element row stride (272B = odd*16B -> ldmatrix conflict-free)

// ---- device scratch (allocation-free rule: __device__ globals) ----
__device__ float g_side[(size_t)N_NODES_MAX * DIM];
__device__ int   g_count[N_NODES_MAX];
__device__ int   g_off[N_NODES_MAX + 1];
__device__ int   g_cur[N_NODES_MAX];
__device__ int   g_ecol[N_EDGES_MAX];
__device__ float g_eval[N_EDGES_MAX];

// ---- smem layout for dense kernel (bf16 elements) ----
#define OFF_SH  0
#define OFF_SL  (OFF_SH  + TILE_M * SA)
#define OFF_PH  (OFF_SL  + TILE_M * SA)
#define OFF_PL  (OFF_PH  + TILE_M * SA)
#define OFF_W1H (OFF_PL  + TILE_M * SA)
#define OFF_W1L (OFF_W1H + DIM * SA)
#define OFF_W2H (OFF_W1L + DIM * SA)
#define OFF_W2L (OFF_W2H + DIM * SA)
#define SMEM_ELEMS (OFF_W2L + DIM * SA)
#define SMEM_BYTES (SMEM_ELEMS * 2)

// ---------------------------------------------------------------------------
// CSR build: histogram -> scan -> fill
// ---------------------------------------------------------------------------
__global__ void hist_kernel(const int* __restrict__ rows, int E) {
    int e = blockIdx.x * blockDim.x + threadIdx.x;
    if (e < E) atomicAdd(&g_count[rows[e]], 1);
}

__global__ void scan_kernel(int n) {
    __shared__ int ssum[1024];
    int t = threadIdx.x;
    int chunk = (n + 1023) / 1024;
    int lo = t * chunk;
    int hi = lo + chunk; if (hi > n) hi = n; if (lo > n) lo = n;

    int s = 0;
    for (int i = lo; i < hi; i++) s += g_count[i];
    ssum[t] = s;
    __syncthreads();
    // Hillis-Steele inclusive scan over 1024 partials
    for (int d = 1; d < 1024; d <<= 1) {
        int v = (t >= d) ? ssum[t - d] : 0;
        __syncthreads();
        ssum[t] += v;
        __syncthreads();
    }
    int run = (t == 0) ? 0 : ssum[t - 1];
    for (int i = lo; i < hi; i++) {
        g_off[i] = run;
        g_cur[i] = run;
        run += g_count[i];
    }
    if (t == 1023) g_off[n] = run;
}

__global__ void fill_kernel(const int* __restrict__ rows,
                            const int* __restrict__ cols,
                            const float* __restrict__ vals, int E) {
    int e = blockIdx.x * blockDim.x + threadIdx.x;
    if (e >= E) return;
    int r = rows[e];
    int p = atomicAdd(&g_cur[r], 1);
    g_ecol[p] = cols[e];
    g_eval[p] = vals[e];
}

// ---------------------------------------------------------------------------
// CSR SpMM: warp per row, register accumulation, single write per row.
//   side[r,:] = sum_e vals[e] * ego[cols[e],:]
// ---------------------------------------------------------------------------
__global__ void spmm_kernel(const float* __restrict__ ego, int n) {
    int w = (blockIdx.x * blockDim.x + threadIdx.x) >> 5;
    if (w >= n) return;
    int lane = threadIdx.x & 31;

    int start = g_off[w];
    int end   = g_off[w + 1];
    const float4* ego4 = reinterpret_cast<const float4*>(ego);

    float4 acc = make_float4(0.f, 0.f, 0.f, 0.f);
    for (int base = start; base < end; base += 32) {
        int e = base + lane;
        int   c = 0;
        float v = 0.f;
        if (e < end) { c = __ldg(&g_ecol[e]); v = __ldg(&g_eval[e]); }
        int m = end - base; if (m > 32) m = 32;
        #pragma unroll 4
        for (int j = 0; j < m; j++) {
            int   cc = __shfl_sync(0xffffffffu, c, j);
            float vv = __shfl_sync(0xffffffffu, v, j);
            float4 x = ego4[(size_t)cc * 32 + lane];
            acc.x += vv * x.x; acc.y += vv * x.y;
            acc.z += vv * x.z; acc.w += vv * x.w;
        }
    }
    reinterpret_cast<float4*>(g_side)[(size_t)w * 32 + lane] = acc;
}

// ---------------------------------------------------------------------------
// mma.sync / ldmatrix helpers
// ---------------------------------------------------------------------------
__device__ __forceinline__ void ldsm_x4(uint32_t* r, uint32_t addr) {
    asm volatile("ldmatrix.sync.aligned.m8n8.x4.shared.b16 {%0,%1,%2,%3}, [%4];"
                 : "=r"(r[0]), "=r"(r[1]), "=r"(r[2]), "=r"(r[3]) : "r"(addr));
}
__device__ __forceinline__ void mma_bf16(float* d, const uint32_t* a,
                                         uint32_t b0, uint32_t b1) {
    asm volatile("mma.sync.aligned.m16n8k16.row.col.f32.bf16.bf16.f32 "
                 "{%0,%1,%2,%3}, {%4,%5,%6,%7}, {%8,%9}, {%0,%1,%2,%3};"
                 : "+f"(d[0]), "+f"(d[1]), "+f"(d[2]), "+f"(d[3])
                 : "r"(a[0]), "r"(a[1]), "r"(a[2]), "r"(a[3]), "r"(b0), "r"(b1));
}
__device__ __forceinline__ float lrelu(float v) { return v > 0.f ? v : 0.01f * v; }

// ---------------------------------------------------------------------------
// Dense kernel (tensor cores, 3-term bf16 split; 16 warps, warp tile 16x32):
//   side_r = bf16_round(side); s = ego + side_r; p = ego * side_r
//   out = lrelu(s @ W1^T + b1) + lrelu(p @ W2^T + b2)
// ---------------------------------------------------------------------------
__global__ void __launch_bounds__(THREADS, 1)
dense_kernel(const float* __restrict__ ego,
             const float* __restrict__ W1, const float* __restrict__ b1,
             const float* __restrict__ W2, const float* __restrict__ b2,
             float* __restrict__ out, int n) {
    extern __shared__ __nv_bfloat16 sm[];
    uint32_t sbase = (uint32_t)__cvta_generic_to_shared(sm);

    int tid  = threadIdx.x;
    int warp = tid >> 5;                 // 0..15
    int lane = tid & 31;
    int warp_m = (warp >> 2) * 16;       // 0,16,32,48
    int warp_n = (warp & 3) * 32;        // 0,32,64,96

    // ---- one-time: split weights to bf16 hi/lo in smem ----
    for (int i = tid; i < DIM * DIM; i += THREADS) {
        int o = i >> 7, k = i & (DIM - 1);
        float w1 = __ldg(&W1[i]);
        float w2 = __ldg(&W2[i]);
        __nv_bfloat16 h1 = __float2bfloat16_rn(w1);
        __nv_bfloat16 h2 = __float2bfloat16_rn(w2);
        sm[OFF_W1H + o * SA + k] = h1;
        sm[OFF_W1L + o * SA + k] = __float2bfloat16_rn(w1 - __bfloat162float(h1));
        sm[OFF_W2H + o * SA + k] = h2;
        sm[OFF_W2L + o * SA + k] = __float2bfloat16_rn(w2 - __bfloat162float(h2));
    }

    // ---- per-thread bias ----
    int col_base = warp_n + (lane & 3) * 2;
    float2 b1v[4], b2v[4];
    #pragma unroll
    for (int nb = 0; nb < 4; nb++) {
        b1v[nb] = *reinterpret_cast<const float2*>(b1 + col_base + nb * 8);
        b2v[nb] = *reinterpret_cast<const float2*>(b2 + col_base + nb * 8);
    }
    __syncthreads();

    // ---- per-thread ldmatrix byte offsets ----
    int lrow = lane & 15;
    int lcol = (lane >> 4) * 8;
    uint32_t a_byte = ((warp_m + lrow) * SA + lcol) * 2;
    uint32_t b_byte[2];
    #pragma unroll
    for (int np = 0; np < 2; np++)
        b_byte[np] = ((warp_n + np * 16 + lrow) * SA + lcol) * 2;

    int numTiles = (n + TILE_M - 1) / TILE_M;
    const float4* ego4  = reinterpret_cast<const float4*>(ego);
    const float4* side4 = reinterpret_cast<const float4*>(g_side);

    for (int tile = blockIdx.x; tile < numTiles; tile += gridDim.x) {
        int row0 = tile * TILE_M;

        // ---- prologue: build split A-tiles (s_hi/s_lo/p_hi/p_lo) ----
        for (int i = tid; i < TILE_M * (DIM / 4); i += THREADS) {
            int r  = i >> 5;
            int c4 = i & 31;
            int row = row0 + r;
            float4 e = make_float4(0.f, 0.f, 0.f, 0.f);
            float4 d = e;
            if (row < n) {
                e = ego4[(size_t)row * 32 + c4];
                d = side4[(size_t)row * 32 + c4];
            }
            // bf16 round-trip of side (matches reference)
            d.x = __bfloat162float(__float2bfloat16(d.x));
            d.y = __bfloat162float(__float2bfloat16(d.y));
            d.z = __bfloat162float(__float2bfloat16(d.z));
            d.w = __bfloat162float(__float2bfloat16(d.w));
            float4 s = make_float4(e.x + d.x, e.y + d.y, e.z + d.z, e.w + d.w);
            float4 p = make_float4(e.x * d.x, e.y * d.y, e.z * d.z, e.w * d.w);

            int off = r * SA + c4 * 4;
            __nv_bfloat162* sh2 = reinterpret_cast<__nv_bfloat162*>(sm + OFF_SH + off);
            __nv_bfloat162* sl2 = reinterpret_cast<__nv_bfloat162*>(sm + OFF_SL + off);
            __nv_bfloat162* ph2 = reinterpret_cast<__nv_bfloat162*>(sm + OFF_PH + off);
            __nv_bfloat162* pl2 = reinterpret_cast<__nv_bfloat162*>(sm + OFF_PL + off);

            __nv_bfloat16 hx, hy, hz, hw;
            hx = __float2bfloat16_rn(s.x); hy = __float2bfloat16_rn(s.y);
            hz = __float2bfloat16_rn(s.z); hw = __float2bfloat16_rn(s.w);
            sh2[0] = __nv_bfloat162(hx, hy);
            sh2[1] = __nv_bfloat162(hz, hw);
            sl2[0] = __nv_bfloat162(__float2bfloat16_rn(s.x - __bfloat162float(hx)),
                                    __float2bfloat16_rn(s.y - __bfloat162float(hy)));
            sl2[1] = __nv_bfloat162(__float2bfloat16_rn(s.z - __bfloat162float(hz)),
                                    __float2bfloat16_rn(s.w - __bfloat162float(hw)));
            hx = __float2bfloat16_rn(p.x); hy = __float2bfloat16_rn(p.y);
            hz = __float2bfloat16_rn(p.z); hw = __float2bfloat16_rn(p.w);
            ph2[0] = __nv_bfloat162(hx, hy);
            ph2[1] = __nv_bfloat162(hz, hw);
            pl2[0] = __nv_bfloat162(__float2bfloat16_rn(p.x - __bfloat162float(hx)),
                                    __float2bfloat16_rn(p.y - __bfloat162float(hy)));
            pl2[1] = __nv_bfloat162(__float2bfloat16_rn(p.z - __bfloat162float(hz)),
                                    __float2bfloat16_rn(p.w - __bfloat162float(hw)));
        }
        __syncthreads();

        // ---- main loop: 8 k-steps of 16 ----
        float d1[4][4];
        float d2[4][4];
        #pragma unroll
        for (int nb = 0; nb < 4; nb++)
            #pragma unroll
            for (int j = 0; j < 4; j++) { d1[nb][j] = 0.f; d2[nb][j] = 0.f; }

        #pragma unroll
        for (int ks = 0; ks < 8; ks++) {
            uint32_t k2 = ks * 32;   // 16 bf16 = 32 bytes

            uint32_t sh[4], sl[4], ph[4], pl[4];
            ldsm_x4(sh, sbase + OFF_SH * 2 + a_byte + k2);
            ldsm_x4(sl, sbase + OFF_SL * 2 + a_byte + k2);
            ldsm_x4(ph, sbase + OFF_PH * 2 + a_byte + k2);
            ldsm_x4(pl, sbase + OFF_PL * 2 + a_byte + k2);

            uint32_t w1h[2][4], w1l[2][4], w2h[2][4], w2l[2][4];
            #pragma unroll
            for (int np = 0; np < 2; np++) {
                ldsm_x4(w1h[np], sbase + OFF_W1H * 2 + b_byte[np] + k2);
                ldsm_x4(w1l[np], sbase + OFF_W1L * 2 + b_byte[np] + k2);
                ldsm_x4(w2h[np], sbase + OFF_W2H * 2 + b_byte[np] + k2);
                ldsm_x4(w2l[np], sbase + OFF_W2L * 2 + b_byte[np] + k2);
            }

            #pragma unroll
            for (int np = 0; np < 2; np++) {
                #pragma unroll
                for (int j = 0; j < 2; j++) {
                    int nb = np * 2 + j;
                    // s path: hi*Whi + lo*Whi + hi*Wlo
                    mma_bf16(d1[nb], sh, w1h[np][j], w1h[np][j + 2]);
                    mma_bf16(d1[nb], sl, w1h[np][j], w1h[np][j + 2]);
                    mma_bf16(d1[nb], sh, w1l[np][j], w1l[np][j + 2]);
                    // p path
                    mma_bf16(d2[nb], ph, w2h[np][j], w2h[np][j + 2]);
                    mma_bf16(d2[nb], pl, w2h[np][j], w2h[np][j + 2]);
                    mma_bf16(d2[nb], ph, w2l[np][j], w2l[np][j + 2]);
                }
            }
        }
        __syncthreads();   // all warps done reading A-tiles before next prologue

        // ---- epilogue: bias + leaky_relu + sum, store fp32 ----
        int r_lo = row0 + warp_m + (lane >> 2);
        int r_hi = r_lo + 8;
        #pragma unroll
        for (int nb = 0; nb < 4; nb++) {
            int col = col_base + nb * 8;
            if (r_lo < n) {
                float2 o;
                o.x = lrelu(d1[nb][0] + b1v[nb].x) + lrelu(d2[nb][0] + b2v[nb].x);
                o.y = lrelu(d1[nb][1] + b1v[nb].y) + lrelu(d2[nb][1] + b2v[nb].y);
                *reinterpret_cast<float2*>(out + (size_t)r_lo * DIM + col) = o;
            }
            if (r_hi < n) {
                float2 o;
                o.x = lrelu(d1[nb][2] + b1v[nb].x) + lrelu(d2[nb][2] + b2v[nb].x);
                o.y = lrelu(d1[nb][3] + b1v[nb].y) + lrelu(d2[nb][3] + b2v[nb].y);
                *reinterpret_cast<float2*>(out + (size_t)r_hi * DIM + col) = o;
            }
        }
    }
}

// ---------------------------------------------------------------------------
extern "C" void kernel_launch(void* const* d_in, const int* in_sizes, int n_in,
                              void* d_out, int out_size) {
    const float* ego  = (const float*)d_in[0];
    const float* vals = (const float*)d_in[1];
    const float* W1   = (const float*)d_in[2];
    const float* b1   = (const float*)d_in[3];
    const float* W2   = (const float*)d_in[4];
    const float* b2   = (const float*)d_in[5];
    const int*   rows = (const int*)d_in[6];
    const int*   cols = (const int*)d_in[7];
    float*       out  = (float*)d_out;

    int n = in_sizes[0] / DIM;   // 50000
    int E = in_sizes[1];         // 640000

    cudaFuncSetAttribute(dense_kernel,
                         cudaFuncAttributeMaxDynamicSharedMemorySize, SMEM_BYTES);

    // 1) CSR build (hist -> scan -> fill)
    void* cnt_ptr = nullptr;
    cudaGetSymbolAddress(&cnt_ptr, g_count);
    cudaMemsetAsync(cnt_ptr, 0, (size_t)n * sizeof(int));
    hist_kernel<<<(E + 255) / 256, 256>>>(rows, E);
    scan_kernel<<<1, 1024>>>(n);
    fill_kernel<<<(E + 255) / 256, 256>>>(rows, cols, vals, E);

    // 2) CSR SpMM (warp per row, writes every g_side row -> no memset needed)
    spmm_kernel<<<(n * 32 + 255) / 256, 256>>>(ego, n);

    // 3) fused dense (tensor cores, 16 warps) — unchanged from R7 control
    dense_kernel<<<148, THREADS, SMEM_BYTES>>>(ego, W1, b1, W2, b2, out, n);
}

// round 10
// speedup vs baseline: 1.4516x; 1.4516x over previous
#include <cuda_runtime.h>
#include <cuda_bf16.h>
#include <cstdint>

#define DIM 128
#define N_NODES_MAX 50000
#define TILE_M 96
#define THREADS 384

// Scratch for the SpMM accumulator (allocation-free rule: __device__ global).
__device__ float g_side[(size_t)N_NODES_MAX * DIM];

// ---- dense smem layout (bytes). Rows are 256B (128 bf16), XOR-swizzled. ----
#define ROWB 256
#define SM_B1   0
#define SM_B2   512
#define SM_A    1024                    // 4 matrices (sh,sl,ph,pl) x 96*256B
#define A_MAT   (TILE_M * ROWB)        // 24576
#define SM_W    (SM_A + 4 * A_MAT)     // 4 matrices (w1h,w1l,w2h,w2l) x 128*256B
#define W_MAT   (DIM * ROWB)           // 32768
#define SMEM_BYTES (SM_W + 4 * W_MAT)  // 230400 = 225KB

// swizzle: XOR the 16B-chunk index (bits 6:4 of the byte column) with row&7
__device__ __forceinline__ uint32_t swz(int r, uint32_t colb) {
    return (uint32_t)r * ROWB + (colb ^ (((uint32_t)r & 7u) << 4));
}

__device__ __forceinline__ uint32_t pack_bf2(float a, float b) {
    __nv_bfloat162 p(__float2bfloat16_rn(a), __float2bfloat16_rn(b));
    return *reinterpret_cast<uint32_t*>(&p);
}

// ---------------------------------------------------------------------------
// Scatter (unchanged control; ~L2-traffic bound)
// ---------------------------------------------------------------------------
__global__ void scatter_kernel(const float* __restrict__ ego,
                               const float* __restrict__ vals,
                               const int*   __restrict__ rows,
                               const int*   __restrict__ cols,
                               int E) {
    int gw = (blockIdx.x * blockDim.x + threadIdx.x) >> 5;
    if (gw >= E) return;
    int lane = threadIdx.x & 31;

    int   c = __ldg(&cols[gw]);
    int   r = __ldg(&rows[gw]);
    float v = __ldg(&vals[gw]);

    float4 x = reinterpret_cast<const float4*>(ego + (size_t)c * DIM)[lane];
    float* dst = g_side + (size_t)r * DIM + lane * 4;
    asm volatile("red.global.add.v4.f32 [%0], {%1,%2,%3,%4};"
                 :: "l"(dst), "f"(v * x.x), "f"(v * x.y), "f"(v * x.z), "f"(v * x.w)
                 : "memory");
}

// ---------------------------------------------------------------------------
// mma.sync / ldmatrix helpers
// ---------------------------------------------------------------------------
__device__ __forceinline__ void ldsm_x4(uint32_t* r, uint32_t addr) {
    asm volatile("ldmatrix.sync.aligned.m8n8.x4.shared.b16 {%0,%1,%2,%3}, [%4];"
                 : "=r"(r[0]), "=r"(r[1]), "=r"(r[2]), "=r"(r[3]) : "r"(addr));
}
__device__ __forceinline__ void mma_bf16(float* d, const uint32_t* a,
                                         uint32_t b0, uint32_t b1) {
    asm volatile("mma.sync.aligned.m16n8k16.row.col.f32.bf16.bf16.f32 "
                 "{%0,%1,%2,%3}, {%4,%5,%6,%7}, {%8,%9}, {%0,%1,%2,%3};"
                 : "+f"(d[0]), "+f"(d[1]), "+f"(d[2]), "+f"(d[3])
                 : "r"(a[0]), "r"(a[1]), "r"(a[2]), "r"(a[3]), "r"(b0), "r"(b1));
}
__device__ __forceinline__ float lrelu(float v) { return v > 0.f ? v : 0.01f * v; }

// ---------------------------------------------------------------------------
// Dense kernel: 12 warps (3m x 4n), warp tile 32x32, TILE_M=96.
//   side_r = bf16_round(side); s = ego + side_r; p = ego * side_r
//   out = lrelu(s @ W1^T + b1) + lrelu(p @ W2^T + b2)   (3-term bf16 split)
// ---------------------------------------------------------------------------
__global__ void __launch_bounds__(THREADS, 1)
dense_kernel(const float* __restrict__ ego,
             const float* __restrict__ W1, const float* __restrict__ b1,
             const float* __restrict__ W2, const float* __restrict__ b2,
             float* __restrict__ out, int n) {
    extern __shared__ char smc[];
    uint32_t sbase = (uint32_t)__cvta_generic_to_shared(smc);

    int tid  = threadIdx.x;
    int warp = tid >> 5;                 // 0..11
    int lane = tid & 31;
    int warp_m = (warp >> 2) * 32;       // 0,32,64
    int warp_n = (warp & 3) * 32;        // 0,32,64,96

    // ---- one-time: split weights into swizzled smem (W[o][k], K-major) ----
    for (int i = tid; i < DIM * DIM; i += THREADS) {
        int o = i >> 7, k = i & 127;
        float w1 = __ldg(&W1[i]);
        float w2 = __ldg(&W2[i]);
        __nv_bfloat16 h1 = __float2bfloat16_rn(w1);
        __nv_bfloat16 h2 = __float2bfloat16_rn(w2);
        uint32_t off = swz(o, (uint32_t)k * 2);
        *reinterpret_cast<__nv_bfloat16*>(smc + SM_W + 0 * W_MAT + off) = h1;
        *reinterpret_cast<__nv_bfloat16*>(smc + SM_W + 1 * W_MAT + off) =
            __float2bfloat16_rn(w1 - __bfloat162float(h1));
        *reinterpret_cast<__nv_bfloat16*>(smc + SM_W + 2 * W_MAT + off) = h2;
        *reinterpret_cast<__nv_bfloat16*>(smc + SM_W + 3 * W_MAT + off) =
            __float2bfloat16_rn(w2 - __bfloat162float(h2));
    }
    for (int i = tid; i < DIM; i += THREADS) {
        reinterpret_cast<float*>(smc + SM_B1)[i] = __ldg(&b1[i]);
        reinterpret_cast<float*>(smc + SM_B2)[i] = __ldg(&b2[i]);
    }
    __syncthreads();

    // ---- per-thread bias (cols owned in mma frags) ----
    int col_base = warp_n + (lane & 3) * 2;
    float2 b1v[4], b2v[4];
    #pragma unroll
    for (int nb = 0; nb < 4; nb++) {
        b1v[nb] = *reinterpret_cast<const float2*>(
                      reinterpret_cast<const float*>(smc + SM_B1) + col_base + nb * 8);
        b2v[nb] = *reinterpret_cast<const float2*>(
                      reinterpret_cast<const float*>(smc + SM_B2) + col_base + nb * 8);
    }

    // ---- per-thread ldmatrix row bases (swizzled col added per k-step) ----
    int lrow = lane & 15;
    int lchunk = (lane >> 4) * 16;       // byte offset of 16B chunk within k
    uint32_t a_addr[2], b_addr[2];
    #pragma unroll
    for (int mb = 0; mb < 2; mb++)
        a_addr[mb] = sbase + SM_A + (uint32_t)(warp_m + mb * 16 + lrow) * ROWB;
    #pragma unroll
    for (int np = 0; np < 2; np++)
        b_addr[np] = sbase + SM_W + (uint32_t)(warp_n + np * 16 + lrow) * ROWB;
    uint32_t xr_a = (uint32_t)((warp_m + lrow) & 7) << 4;   // mb*16 preserves r&7
    uint32_t xr_b = (uint32_t)((warp_n + lrow) & 7) << 4;

    int numTiles = (n + TILE_M - 1) / TILE_M;
    const float4* ego4  = reinterpret_cast<const float4*>(ego);
    const float4* side4 = reinterpret_cast<const float4*>(g_side);

    for (int tile = blockIdx.x; tile < numTiles; tile += gridDim.x) {
        int row0 = tile * TILE_M;

        // ---- prologue: build sh/sl/ph/pl (96 rows x 32 float4) ----
        for (int i = tid; i < TILE_M * 32; i += THREADS) {
            int r  = i >> 5;
            int c4 = i & 31;
            int row = row0 + r;
            float4 e = make_float4(0.f, 0.f, 0.f, 0.f);
            float4 d = e;
            if (row < n) {
                e = ego4[(size_t)row * 32 + c4];
                d = side4[(size_t)row * 32 + c4];
            }
            d.x = __bfloat162float(__float2bfloat16(d.x));
            d.y = __bfloat162float(__float2bfloat16(d.y));
            d.z = __bfloat162float(__float2bfloat16(d.z));
            d.w = __bfloat162float(__float2bfloat16(d.w));
            float4 s = make_float4(e.x + d.x, e.y + d.y, e.z + d.z, e.w + d.w);
            float4 p = make_float4(e.x * d.x, e.y * d.y, e.z * d.z, e.w * d.w);

            uint32_t off = swz(r, (uint32_t)c4 * 8);   // 4 bf16 = 8 bytes
            float shx = __bfloat162float(__float2bfloat16_rn(s.x));
            float shy = __bfloat162float(__float2bfloat16_rn(s.y));
            float shz = __bfloat162float(__float2bfloat16_rn(s.z));
            float shw = __bfloat162float(__float2bfloat16_rn(s.w));
            uint2 u;
            u.x = pack_bf2(s.x, s.y); u.y = pack_bf2(s.z, s.w);
            *reinterpret_cast<uint2*>(smc + SM_A + 0 * A_MAT + off) = u;
            u.x = pack_bf2(s.x - shx, s.y - shy); u.y = pack_bf2(s.z - shz, s.w - shw);
            *reinterpret_cast<uint2*>(smc + SM_A + 1 * A_MAT + off) = u;

            float phx = __bfloat162float(__float2bfloat16_rn(p.x));
            float phy = __bfloat162float(__float2bfloat16_rn(p.y));
            float phz = __bfloat162float(__float2bfloat16_rn(p.z));
            float phw = __bfloat162float(__float2bfloat16_rn(p.w));
            u.x = pack_bf2(p.x, p.y); u.y = pack_bf2(p.z, p.w);
            *reinterpret_cast<uint2*>(smc + SM_A + 2 * A_MAT + off) = u;
            u.x = pack_bf2(p.x - phx, p.y - phy); u.y = pack_bf2(p.z - phz, p.w - phw);
            *reinterpret_cast<uint2*>(smc + SM_A + 3 * A_MAT + off) = u;
        }
        __syncthreads();

        // ---- main loop: 8 k-steps ----
        float d1[2][4][4], d2[2][4][4];
        #pragma unroll
        for (int mb = 0; mb < 2; mb++)
            #pragma unroll
            for (int nb = 0; nb < 4; nb++)
                #pragma unroll
                for (int j = 0; j < 4; j++) { d1[mb][nb][j] = 0.f; d2[mb][nb][j] = 0.f; }

        #pragma unroll
        for (int ks = 0; ks < 8; ks++) {
            uint32_t kA = ((uint32_t)(ks * 32 + lchunk)) ^ xr_a;
            uint32_t kB = ((uint32_t)(ks * 32 + lchunk)) ^ xr_b;

            uint32_t sh[2][4], sl[2][4], ph[2][4], pl[2][4];
            #pragma unroll
            for (int mb = 0; mb < 2; mb++) {
                ldsm_x4(sh[mb], a_addr[mb] + 0 * A_MAT + kA);
                ldsm_x4(sl[mb], a_addr[mb] + 1 * A_MAT + kA);
                ldsm_x4(ph[mb], a_addr[mb] + 2 * A_MAT + kA);
                ldsm_x4(pl[mb], a_addr[mb] + 3 * A_MAT + kA);
            }
            uint32_t w1h[2][4], w1l[2][4], w2h[2][4], w2l[2][4];
            #pragma unroll
            for (int np = 0; np < 2; np++) {
                ldsm_x4(w1h[np], b_addr[np] + 0 * W_MAT + kB);
                ldsm_x4(w1l[np], b_addr[np] + 1 * W_MAT + kB);
                ldsm_x4(w2h[np], b_addr[np] + 2 * W_MAT + kB);
                ldsm_x4(w2l[np], b_addr[np] + 3 * W_MAT + kB);
            }

            #pragma unroll
            for (int mb = 0; mb < 2; mb++) {
                #pragma unroll
                for (int np = 0; np < 2; np++) {
                    #pragma unroll
                    for (int j = 0; j < 2; j++) {
                        int nb = np * 2 + j;
                        mma_bf16(d1[mb][nb], sh[mb], w1h[np][j], w1h[np][j + 2]);
                        mma_bf16(d1[mb][nb], sl[mb], w1h[np][j], w1h[np][j + 2]);
                        mma_bf16(d1[mb][nb], sh[mb], w1l[np][j], w1l[np][j + 2]);
                        mma_bf16(d2[mb][nb], ph[mb], w2h[np][j], w2h[np][j + 2]);
                        mma_bf16(d2[mb][nb], pl[mb], w2h[np][j], w2h[np][j + 2]);
                        mma_bf16(d2[mb][nb], ph[mb], w2l[np][j], w2l[np][j + 2]);
                    }
                }
            }
        }
        __syncthreads();   // all warps done reading A-tiles before next prologue

        // ---- epilogue: bias + leaky_relu + sum, store fp32 ----
        #pragma unroll
        for (int mb = 0; mb < 2; mb++) {
            int r_lo = row0 + warp_m + mb * 16 + (lane >> 2);
            int r_hi = r_lo + 8;
            #pragma unroll
            for (int nb = 0; nb < 4; nb++) {
                int col = col_base + nb * 8;
                if (r_lo < n) {
                    float2 o;
                    o.x = lrelu(d1[mb][nb][0] + b1v[nb].x) + lrelu(d2[mb][nb][0] + b2v[nb].x);
                    o.y = lrelu(d1[mb][nb][1] + b1v[nb].y) + lrelu(d2[mb][nb][1] + b2v[nb].y);
                    *reinterpret_cast<float2*>(out + (size_t)r_lo * DIM + col) = o;
                }
                if (r_hi < n) {
                    float2 o;
                    o.x = lrelu(d1[mb][nb][2] + b1v[nb].x) + lrelu(d2[mb][nb][2] + b2v[nb].x);
                    o.y = lrelu(d1[mb][nb][3] + b1v[nb].y) + lrelu(d2[mb][nb][3] + b2v[nb].y);
                    *reinterpret_cast<float2*>(out + (size_t)r_hi * DIM + col) = o;
                }
            }
        }
    }
}

// ---------------------------------------------------------------------------
extern "C" void kernel_launch(void* const* d_in, const int* in_sizes, int n_in,
                              void* d_out, int out_size) {
    const float* ego  = (const float*)d_in[0];
    const float* vals = (const float*)d_in[1];
    const float* W1   = (const float*)d_in[2];
    const float* b1   = (const float*)d_in[3];
    const float* W2   = (const float*)d_in[4];
    const float* b2   = (const float*)d_in[5];
    const int*   rows = (const int*)d_in[6];
    const int*   cols = (const int*)d_in[7];
    float*       out  = (float*)d_out;

    int n = in_sizes[0] / DIM;   // 50000
    int E = in_sizes[1];         // 640000

    cudaFuncSetAttribute(dense_kernel,
                         cudaFuncAttributeMaxDynamicSharedMemorySize, SMEM_BYTES);

    // 1) zero scratch
    void* side_ptr = nullptr;
    cudaGetSymbolAddress(&side_ptr, g_side);
    cudaMemsetAsync(side_ptr, 0, (size_t)n * DIM * sizeof(float));

    // 2) edge scatter
    int blocks = (E + 7) / 8;
    scatter_kernel<<<blocks, 256>>>(ego, vals, rows, cols, E);

    // 3) fused dense (mma.sync, 12 warps, TILE_M=96, swizzled smem)
    dense_kernel<<<148, THREADS, SMEM_BYTES>>>(ego, W1, b1, W2, b2, out, n);
}

// round 11
// speedup vs baseline: 1.8785x; 1.2941x over previous
#include <cuda_runtime.h>
#include <cuda_bf16.h>
#include <cstdint>

#define DIM 128
#define N_NODES_MAX 50000
#define N_EDGES_MAX 640000
#define BUCKET 64
#define TILE_M 96
#define THREADS 384

// ---- device scratch (allocation-free rule: __device__ globals) ----
__device__ float g_side[(size_t)N_NODES_MAX * DIM];
__device__ int   g_cnt[N_NODES_MAX];
__device__ uint2 g_bucket[(size_t)N_NODES_MAX * BUCKET];   // (col, val) per slot
__device__ int   g_ovf_cnt;
__device__ uint4 g_ovf[N_EDGES_MAX];                       // (row, col, val, 0)

// ---- dense smem layout (bytes). Rows are 256B (128 bf16), XOR-swizzled. ----
#define ROWB 256
#define SM_B1   0
#define SM_B2   512
#define SM_A    1024
#define A_MAT   (TILE_M * ROWB)
#define SM_W    (SM_A + 4 * A_MAT)
#define W_MAT   (DIM * ROWB)
#define SMEM_BYTES (SM_W + 4 * W_MAT)   // 230400 B

__device__ __forceinline__ uint32_t swz(int r, uint32_t colb) {
    return (uint32_t)r * ROWB + (colb ^ (((uint32_t)r & 7u) << 4));
}
__device__ __forceinline__ uint32_t pack_bf2(float a, float b) {
    __nv_bfloat162 p(__float2bfloat16_rn(a), __float2bfloat16_rn(b));
    return *reinterpret_cast<uint32_t*>(&p);
}

// ---------------------------------------------------------------------------
// Bucket fill: one thread per edge; atomic cursor per row, no scan.
// ---------------------------------------------------------------------------
__global__ void bucket_fill(const int* __restrict__ rows,
                            const int* __restrict__ cols,
                            const float* __restrict__ vals, int E) {
    int e = blockIdx.x * blockDim.x + threadIdx.x;
    if (e >= E) return;
    int r = __ldg(&rows[e]);
    int c = __ldg(&cols[e]);
    float v = __ldg(&vals[e]);
    int p = atomicAdd(&g_cnt[r], 1);
    if (p < BUCKET) {
        g_bucket[(size_t)r * BUCKET + p] = make_uint2((uint32_t)c, __float_as_uint(v));
    } else {
        int q = atomicAdd(&g_ovf_cnt, 1);
        g_ovf[q] = make_uint4((uint32_t)r, (uint32_t)c, __float_as_uint(v), 0u);
    }
}

// ---------------------------------------------------------------------------
// Bucket SpMM: warp per row; register accumulate; single plain write per row.
// ---------------------------------------------------------------------------
__global__ void spmm_bucket(const float* __restrict__ ego, int n) {
    int w = (blockIdx.x * blockDim.x + threadIdx.x) >> 5;
    if (w >= n) return;
    int lane = threadIdx.x & 31;

    int deg = g_cnt[w];
    if (deg > BUCKET) deg = BUCKET;
    const float4* ego4 = reinterpret_cast<const float4*>(ego);

    float4 acc = make_float4(0.f, 0.f, 0.f, 0.f);
    for (int base = 0; base < deg; base += 32) {
        uint2 slot = make_uint2(0u, 0u);
        if (base + lane < deg)
            slot = __ldg(&g_bucket[(size_t)w * BUCKET + base + lane]);
        int m = deg - base; if (m > 32) m = 32;
        #pragma unroll 4
        for (int j = 0; j < m; j++) {
            uint32_t cc = __shfl_sync(0xffffffffu, slot.x, j);
            float    vv = __uint_as_float(__shfl_sync(0xffffffffu, slot.y, j));
            float4 x = ego4[(size_t)cc * 32 + lane];
            acc.x += vv * x.x; acc.y += vv * x.y;
            acc.z += vv * x.z; acc.w += vv * x.w;
        }
    }
    reinterpret_cast<float4*>(g_side)[(size_t)w * 32 + lane] = acc;
}

// ---------------------------------------------------------------------------
// Overflow fixup: runs AFTER spmm_bucket; red.adds rare overflow edges.
// ---------------------------------------------------------------------------
__global__ void ovf_fixup(const float* __restrict__ ego) {
    int total = g_ovf_cnt;
    int gw = (blockIdx.x * blockDim.x + threadIdx.x) >> 5;
    int nw = (gridDim.x * blockDim.x) >> 5;
    int lane = threadIdx.x & 31;
    const float4* ego4 = reinterpret_cast<const float4*>(ego);
    for (int i = gw; i < total; i += nw) {
        uint4 t = g_ovf[i];
        float v = __uint_as_float(t.z);
        float4 x = ego4[(size_t)t.y * 32 + lane];
        float* dst = g_side + (size_t)t.x * DIM + lane * 4;
        asm volatile("red.global.add.v4.f32 [%0], {%1,%2,%3,%4};"
                     :: "l"(dst), "f"(v * x.x), "f"(v * x.y), "f"(v * x.z), "f"(v * x.w)
                     : "memory");
    }
}

// ---------------------------------------------------------------------------
// mma.sync / ldmatrix helpers
// ---------------------------------------------------------------------------
__device__ __forceinline__ void ldsm_x4(uint32_t* r, uint32_t addr) {
    asm volatile("ldmatrix.sync.aligned.m8n8.x4.shared.b16 {%0,%1,%2,%3}, [%4];"
                 : "=r"(r[0]), "=r"(r[1]), "=r"(r[2]), "=r"(r[3]) : "r"(addr));
}
__device__ __forceinline__ void mma_bf16(float* d, const uint32_t* a,
                                         uint32_t b0, uint32_t b1) {
    asm volatile("mma.sync.aligned.m16n8k16.row.col.f32.bf16.bf16.f32 "
                 "{%0,%1,%2,%3}, {%4,%5,%6,%7}, {%8,%9}, {%0,%1,%2,%3};"
                 : "+f"(d[0]), "+f"(d[1]), "+f"(d[2]), "+f"(d[3])
                 : "r"(a[0]), "r"(a[1]), "r"(a[2]), "r"(a[3]), "r"(b0), "r"(b1));
}
__device__ __forceinline__ float lrelu(float v) { return v > 0.f ? v : 0.01f * v; }

// ---------------------------------------------------------------------------
// Dense kernel (R10 control, unchanged): 12 warps (3m x 4n), TILE_M=96.
// ---------------------------------------------------------------------------
__global__ void __launch_bounds__(THREADS, 1)
dense_kernel(const float* __restrict__ ego,
             const float* __restrict__ W1, const float* __restrict__ b1,
             const float* __restrict__ W2, const float* __restrict__ b2,
             float* __restrict__ out, int n) {
    extern __shared__ char smc[];
    uint32_t sbase = (uint32_t)__cvta_generic_to_shared(smc);

    int tid  = threadIdx.x;
    int warp = tid >> 5;
    int lane = tid & 31;
    int warp_m = (warp >> 2) * 32;
    int warp_n = (warp & 3) * 32;

    for (int i = tid; i < DIM * DIM; i += THREADS) {
        int o = i >> 7, k = i & 127;
        float w1 = __ldg(&W1[i]);
        float w2 = __ldg(&W2[i]);
        __nv_bfloat16 h1 = __float2bfloat16_rn(w1);
        __nv_bfloat16 h2 = __float2bfloat16_rn(w2);
        uint32_t off = swz(o, (uint32_t)k * 2);
        *reinterpret_cast<__nv_bfloat16*>(smc + SM_W + 0 * W_MAT + off) = h1;
        *reinterpret_cast<__nv_bfloat16*>(smc + SM_W + 1 * W_MAT + off) =
            __float2bfloat16_rn(w1 - __bfloat162float(h1));
        *reinterpret_cast<__nv_bfloat16*>(smc + SM_W + 2 * W_MAT + off) = h2;
        *reinterpret_cast<__nv_bfloat16*>(smc + SM_W + 3 * W_MAT + off) =
            __float2bfloat16_rn(w2 - __bfloat162float(h2));
    }
    for (int i = tid; i < DIM; i += THREADS) {
        reinterpret_cast<float*>(smc + SM_B1)[i] = __ldg(&b1[i]);
        reinterpret_cast<float*>(smc + SM_B2)[i] = __ldg(&b2[i]);
    }
    __syncthreads();

    int col_base = warp_n + (lane & 3) * 2;
    float2 b1v[4], b2v[4];
    #pragma unroll
    for (int nb = 0; nb < 4; nb++) {
        b1v[nb] = *reinterpret_cast<const float2*>(
                      reinterpret_cast<const float*>(smc + SM_B1) + col_base + nb * 8);
        b2v[nb] = *reinterpret_cast<const float2*>(
                      reinterpret_cast<const float*>(smc + SM_B2) + col_base + nb * 8);
    }

    int lrow = lane & 15;
    int lchunk = (lane >> 4) * 16;
    uint32_t a_addr[2], b_addr[2];
    #pragma unroll
    for (int mb = 0; mb < 2; mb++)
        a_addr[mb] = sbase + SM_A + (uint32_t)(warp_m + mb * 16 + lrow) * ROWB;
    #pragma unroll
    for (int np = 0; np < 2; np++)
        b_addr[np] = sbase + SM_W + (uint32_t)(warp_n + np * 16 + lrow) * ROWB;
    uint32_t xr_a = (uint32_t)((warp_m + lrow) & 7) << 4;
    uint32_t xr_b = (uint32_t)((warp_n + lrow) & 7) << 4;

    int numTiles = (n + TILE_M - 1) / TILE_M;
    const float4* ego4  = reinterpret_cast<const float4*>(ego);
    const float4* side4 = reinterpret_cast<const float4*>(g_side);

    for (int tile = blockIdx.x; tile < numTiles; tile += gridDim.x) {
        int row0 = tile * TILE_M;

        for (int i = tid; i < TILE_M * 32; i += THREADS) {
            int r  = i >> 5;
            int c4 = i & 31;
            int row = row0 + r;
            float4 e = make_float4(0.f, 0.f, 0.f, 0.f);
            float4 d = e;
            if (row < n) {
                e = ego4[(size_t)row * 32 + c4];
                d = side4[(size_t)row * 32 + c4];
            }
            d.x = __bfloat162float(__float2bfloat16(d.x));
            d.y = __bfloat162float(__float2bfloat16(d.y));
            d.z = __bfloat162float(__float2bfloat16(d.z));
            d.w = __bfloat162float(__float2bfloat16(d.w));
            float4 s = make_float4(e.x + d.x, e.y + d.y, e.z + d.z, e.w + d.w);
            float4 p = make_float4(e.x * d.x, e.y * d.y, e.z * d.z, e.w * d.w);

            uint32_t off = swz(r, (uint32_t)c4 * 8);
            float shx = __bfloat162float(__float2bfloat16_rn(s.x));
            float shy = __bfloat162float(__float2bfloat16_rn(s.y));
            float shz = __bfloat162float(__float2bfloat16_rn(s.z));
            float shw = __bfloat162float(__float2bfloat16_rn(s.w));
            uint2 u;
            u.x = pack_bf2(s.x, s.y); u.y = pack_bf2(s.z, s.w);
            *reinterpret_cast<uint2*>(smc + SM_A + 0 * A_MAT + off) = u;
            u.x = pack_bf2(s.x - shx, s.y - shy); u.y = pack_bf2(s.z - shz, s.w - shw);
            *reinterpret_cast<uint2*>(smc + SM_A + 1 * A_MAT + off) = u;

            float phx = __bfloat162float(__float2bfloat16_rn(p.x));
            float phy = __bfloat162float(__float2bfloat16_rn(p.y));
            float phz = __bfloat162float(__float2bfloat16_rn(p.z));
            float phw = __bfloat162float(__float2bfloat16_rn(p.w));
            u.x = pack_bf2(p.x, p.y); u.y = pack_bf2(p.z, p.w);
            *reinterpret_cast<uint2*>(smc + SM_A + 2 * A_MAT + off) = u;
            u.x = pack_bf2(p.x - phx, p.y - phy); u.y = pack_bf2(p.z - phz, p.w - phw);
            *reinterpret_cast<uint2*>(smc + SM_A + 3 * A_MAT + off) = u;
        }
        __syncthreads();

        float d1[2][4][4], d2[2][4][4];
        #pragma unroll
        for (int mb = 0; mb < 2; mb++)
            #pragma unroll
            for (int nb = 0; nb < 4; nb++)
                #pragma unroll
                for (int j = 0; j < 4; j++) { d1[mb][nb][j] = 0.f; d2[mb][nb][j] = 0.f; }

        #pragma unroll
        for (int ks = 0; ks < 8; ks++) {
            uint32_t kA = ((uint32_t)(ks * 32 + lchunk)) ^ xr_a;
            uint32_t kB = ((uint32_t)(ks * 32 + lchunk)) ^ xr_b;

            uint32_t sh[2][4], sl[2][4], ph[2][4], pl[2][4];
            #pragma unroll
            for (int mb = 0; mb < 2; mb++) {
                ldsm_x4(sh[mb], a_addr[mb] + 0 * A_MAT + kA);
                ldsm_x4(sl[mb], a_addr[mb] + 1 * A_MAT + kA);
                ldsm_x4(ph[mb], a_addr[mb] + 2 * A_MAT + kA);
                ldsm_x4(pl[mb], a_addr[mb] + 3 * A_MAT + kA);
            }
            uint32_t w1h[2][4], w1l[2][4], w2h[2][4], w2l[2][4];
            #pragma unroll
            for (int np = 0; np < 2; np++) {
                ldsm_x4(w1h[np], b_addr[np] + 0 * W_MAT + kB);
                ldsm_x4(w1l[np], b_addr[np] + 1 * W_MAT + kB);
                ldsm_x4(w2h[np], b_addr[np] + 2 * W_MAT + kB);
                ldsm_x4(w2l[np], b_addr[np] + 3 * W_MAT + kB);
            }

            #pragma unroll
            for (int mb = 0; mb < 2; mb++) {
                #pragma unroll
                for (int np = 0; np < 2; np++) {
                    #pragma unroll
                    for (int j = 0; j < 2; j++) {
                        int nb = np * 2 + j;
                        mma_bf16(d1[mb][nb], sh[mb], w1h[np][j], w1h[np][j + 2]);
                        mma_bf16(d1[mb][nb], sl[mb], w1h[np][j], w1h[np][j + 2]);
                        mma_bf16(d1[mb][nb], sh[mb], w1l[np][j], w1l[np][j + 2]);
                        mma_bf16(d2[mb][nb], ph[mb], w2h[np][j], w2h[np][j + 2]);
                        mma_bf16(d2[mb][nb], pl[mb], w2h[np][j], w2h[np][j + 2]);
                        mma_bf16(d2[mb][nb], ph[mb], w2l[np][j], w2l[np][j + 2]);
                    }
                }
            }
        }
        __syncthreads();

        #pragma unroll
        for (int mb = 0; mb < 2; mb++) {
            int r_lo = row0 + warp_m + mb * 16 + (lane >> 2);
            int r_hi = r_lo + 8;
            #pragma unroll
            for (int nb = 0; nb < 4; nb++) {
                int col = col_base + nb * 8;
                if (r_lo < n) {
                    float2 o;
                    o.x = lrelu(d1[mb][nb][0] + b1v[nb].x) + lrelu(d2[mb][nb][0] + b2v[nb].x);
                    o.y = lrelu(d1[mb][nb][1] + b1v[nb].y) + lrelu(d2[mb][nb][1] + b2v[nb].y);
                    *reinterpret_cast<float2*>(out + (size_t)r_lo * DIM + col) = o;
                }
                if (r_hi < n) {
                    float2 o;
                    o.x = lrelu(d1[mb][nb][2] + b1v[nb].x) + lrelu(d2[mb][nb][2] + b2v[nb].x);
                    o.y = lrelu(d1[mb][nb][3] + b1v[nb].y) + lrelu(d2[mb][nb][3] + b2v[nb].y);
                    *reinterpret_cast<float2*>(out + (size_t)r_hi * DIM + col) = o;
                }
            }
        }
    }
}

// ---------------------------------------------------------------------------
extern "C" void kernel_launch(void* const* d_in, const int* in_sizes, int n_in,
                              void* d_out, int out_size) {
    const float* ego  = (const float*)d_in[0];
    const float* vals = (const float*)d_in[1];
    const float* W1   = (const float*)d_in[2];
    const float* b1   = (const float*)d_in[3];
    const float* W2   = (const float*)d_in[4];
    const float* b2   = (const float*)d_in[5];
    const int*   rows = (const int*)d_in[6];
    const int*   cols = (const int*)d_in[7];
    float*       out  = (float*)d_out;

    int n = in_sizes[0] / DIM;   // 50000
    int E = in_sizes[1];         // 640000

    cudaFuncSetAttribute(dense_kernel,
                         cudaFuncAttributeMaxDynamicSharedMemorySize, SMEM_BYTES);

    // 1) reset bucket cursors + overflow counter
    void* cnt_ptr = nullptr;
    cudaGetSymbolAddress(&cnt_ptr, g_cnt);
    cudaMemsetAsync(cnt_ptr, 0, (size_t)n * sizeof(int));
    void* ovf_ptr = nullptr;
    cudaGetSymbolAddress(&ovf_ptr, g_ovf_cnt);
    cudaMemsetAsync(ovf_ptr, 0, sizeof(int));

    // 2) bucket fill (one thread per edge, atomic cursor, no scan)
    bucket_fill<<<(E + 255) / 256, 256>>>(rows, cols, vals, E);

    // 3) bucket SpMM (warp per row, plain single write per row)
    spmm_bucket<<<(n * 32 + 255) / 256, 256>>>(ego, n);

    // 4) overflow fixup (usually empty; correctness for any degree dist.)
    ovf_fixup<<<64, 256>>>(ego);

    // 5) fused dense (unchanged R10 control)
    dense_kernel<<<148, THREADS, SMEM_BYTES>>>(ego, W1, b1, W2, b2, out, n);
}

// round 12
// speedup vs baseline: 2.0455x; 1.0889x over previous
#include <cuda_runtime.h>
#include <cuda_bf16.h>
#include <cstdint>

#define DIM 128
#define N_NODES_MAX 50000
#define N_EDGES_MAX 640000
#define BUCKET 64
#define TILE_M 32
#define NBUF 3
#define THREADS 384

// ---- device scratch (allocation-free rule: __device__ globals) ----
__device__ float g_side[(size_t)N_NODES_MAX * DIM];
__device__ int   g_cnt[N_NODES_MAX];
__device__ uint2 g_bucket[(size_t)N_NODES_MAX * BUCKET];
__device__ int   g_ovf_cnt;
__device__ uint4 g_ovf[N_EDGES_MAX];

// ---- dense smem layout (bytes). Rows 256B (128 bf16), XOR-swizzled. ----
#define ROWB 256
#define A_MAT8 (TILE_M * ROWB)          // 8192 per matrix
#define A_BUF  (4 * A_MAT8)             // 32768 per buffer (sh,sl,ph,pl)
#define SM_B1  0
#define SM_B2  512
#define SM_A   1024
#define SM_W   (SM_A + NBUF * A_BUF)    // 1024 + 98304 = 99328
#define W_MAT  (DIM * ROWB)             // 32768
#define SMEM_BYTES (SM_W + 4 * W_MAT)   // 230400

__device__ __forceinline__ uint32_t swz(int r, uint32_t colb) {
    return (uint32_t)r * ROWB + (colb ^ (((uint32_t)r & 7u) << 4));
}
__device__ __forceinline__ uint32_t pack_bf2(float a, float b) {
    __nv_bfloat162 p(__float2bfloat16_rn(a), __float2bfloat16_rn(b));
    return *reinterpret_cast<uint32_t*>(&p);
}
__device__ __forceinline__ void bar_syn(int id, int cnt) {
    asm volatile("bar.sync %0, %1;" :: "r"(id), "r"(cnt) : "memory");
}
__device__ __forceinline__ void bar_arr(int id, int cnt) {
    asm volatile("bar.arrive %0, %1;" :: "r"(id), "r"(cnt) : "memory");
}

// ---------------------------------------------------------------------------
// Bucket fill / SpMM / overflow fixup (unchanged R11 control)
// ---------------------------------------------------------------------------
__global__ void bucket_fill(const int* __restrict__ rows,
                            const int* __restrict__ cols,
                            const float* __restrict__ vals, int E) {
    int e = blockIdx.x * blockDim.x + threadIdx.x;
    if (e >= E) return;
    int r = __ldg(&rows[e]);
    int c = __ldg(&cols[e]);
    float v = __ldg(&vals[e]);
    int p = atomicAdd(&g_cnt[r], 1);
    if (p < BUCKET) {
        g_bucket[(size_t)r * BUCKET + p] = make_uint2((uint32_t)c, __float_as_uint(v));
    } else {
        int q = atomicAdd(&g_ovf_cnt, 1);
        g_ovf[q] = make_uint4((uint32_t)r, (uint32_t)c, __float_as_uint(v), 0u);
    }
}

__global__ void spmm_bucket(const float* __restrict__ ego, int n) {
    int w = (blockIdx.x * blockDim.x + threadIdx.x) >> 5;
    if (w >= n) return;
    int lane = threadIdx.x & 31;

    int deg = g_cnt[w];
    if (deg > BUCKET) deg = BUCKET;
    const float4* ego4 = reinterpret_cast<const float4*>(ego);

    float4 acc = make_float4(0.f, 0.f, 0.f, 0.f);
    for (int base = 0; base < deg; base += 32) {
        uint2 slot = make_uint2(0u, 0u);
        if (base + lane < deg)
            slot = __ldg(&g_bucket[(size_t)w * BUCKET + base + lane]);
        int m = deg - base; if (m > 32) m = 32;
        #pragma unroll 4
        for (int j = 0; j < m; j++) {
            uint32_t cc = __shfl_sync(0xffffffffu, slot.x, j);
            float    vv = __uint_as_float(__shfl_sync(0xffffffffu, slot.y, j));
            float4 x = ego4[(size_t)cc * 32 + lane];
            acc.x += vv * x.x; acc.y += vv * x.y;
            acc.z += vv * x.z; acc.w += vv * x.w;
        }
    }
    reinterpret_cast<float4*>(g_side)[(size_t)w * 32 + lane] = acc;
}

__global__ void ovf_fixup(const float* __restrict__ ego) {
    int total = g_ovf_cnt;
    int gw = (blockIdx.x * blockDim.x + threadIdx.x) >> 5;
    int nw = (gridDim.x * blockDim.x) >> 5;
    int lane = threadIdx.x & 31;
    const float4* ego4 = reinterpret_cast<const float4*>(ego);
    for (int i = gw; i < total; i += nw) {
        uint4 t = g_ovf[i];
        float v = __uint_as_float(t.z);
        float4 x = ego4[(size_t)t.y * 32 + lane];
        float* dst = g_side + (size_t)t.x * DIM + lane * 4;
        asm volatile("red.global.add.v4.f32 [%0], {%1,%2,%3,%4};"
                     :: "l"(dst), "f"(v * x.x), "f"(v * x.y), "f"(v * x.z), "f"(v * x.w)
                     : "memory");
    }
}

// ---------------------------------------------------------------------------
// mma.sync / ldmatrix helpers
// ---------------------------------------------------------------------------
__device__ __forceinline__ void ldsm_x4(uint32_t* r, uint32_t addr) {
    asm volatile("ldmatrix.sync.aligned.m8n8.x4.shared.b16 {%0,%1,%2,%3}, [%4];"
                 : "=r"(r[0]), "=r"(r[1]), "=r"(r[2]), "=r"(r[3]) : "r"(addr));
}
__device__ __forceinline__ void mma_bf16(float* d, const uint32_t* a,
                                         uint32_t b0, uint32_t b1) {
    asm volatile("mma.sync.aligned.m16n8k16.row.col.f32.bf16.bf16.f32 "
                 "{%0,%1,%2,%3}, {%4,%5,%6,%7}, {%8,%9}, {%0,%1,%2,%3};"
                 : "+f"(d[0]), "+f"(d[1]), "+f"(d[2]), "+f"(d[3])
                 : "r"(a[0]), "r"(a[1]), "r"(a[2]), "r"(a[3]), "r"(b0), "r"(b1));
}
__device__ __forceinline__ float lrelu(float v) { return v > 0.f ? v : 0.01f * v; }

// ---------------------------------------------------------------------------
// Dense kernel: warp-specialized. Warps 0-7 MMA consumers (2m x 4n, 16x32),
// warps 8-11 producers converting the next tile into a 3-deep buffer ring.
// ---------------------------------------------------------------------------
__global__ void __launch_bounds__(THREADS, 1)
dense_kernel(const float* __restrict__ ego,
             const float* __restrict__ W1, const float* __restrict__ b1,
             const float* __restrict__ W2, const float* __restrict__ b2,
             float* __restrict__ out, int n) {
    extern __shared__ char smc[];
    uint32_t sbase = (uint32_t)__cvta_generic_to_shared(smc);

    int tid  = threadIdx.x;
    int warp = tid >> 5;
    int lane = tid & 31;

    // ---- one-time: split weights into swizzled smem (all 384 threads) ----
    for (int i = tid; i < DIM * DIM; i += THREADS) {
        int o = i >> 7, k = i & 127;
        float w1 = __ldg(&W1[i]);
        float w2 = __ldg(&W2[i]);
        __nv_bfloat16 h1 = __float2bfloat16_rn(w1);
        __nv_bfloat16 h2 = __float2bfloat16_rn(w2);
        uint32_t off = swz(o, (uint32_t)k * 2);
        *reinterpret_cast<__nv_bfloat16*>(smc + SM_W + 0 * W_MAT + off) = h1;
        *reinterpret_cast<__nv_bfloat16*>(smc + SM_W + 1 * W_MAT + off) =
            __float2bfloat16_rn(w1 - __bfloat162float(h1));
        *reinterpret_cast<__nv_bfloat16*>(smc + SM_W + 2 * W_MAT + off) = h2;
        *reinterpret_cast<__nv_bfloat16*>(smc + SM_W + 3 * W_MAT + off) =
            __float2bfloat16_rn(w2 - __bfloat162float(h2));
    }
    for (int i = tid; i < DIM; i += THREADS) {
        reinterpret_cast<float*>(smc + SM_B1)[i] = __ldg(&b1[i]);
        reinterpret_cast<float*>(smc + SM_B2)[i] = __ldg(&b2[i]);
    }
    __syncthreads();

    int nt = (n + TILE_M - 1) / TILE_M;
    const float4* ego4  = reinterpret_cast<const float4*>(ego);
    const float4* side4 = reinterpret_cast<const float4*>(g_side);

    if (warp >= 8) {
        // ================= PRODUCER (warps 8-11, 128 threads) =================
        int pt = tid - 256;
        int k = 0;
        for (int t = blockIdx.x; t < nt; t += gridDim.x, k++) {
            int b = k % NBUF;
            if (k >= NBUF) bar_syn(4 + b, THREADS);   // wait buffer free
            char* abuf = smc + SM_A + b * A_BUF;
            int row0 = t * TILE_M;

            for (int i = pt; i < TILE_M * 32; i += 128) {
                int r  = i >> 5;
                int c4 = i & 31;
                int row = row0 + r;
                float4 e = make_float4(0.f, 0.f, 0.f, 0.f);
                float4 d = e;
                if (row < n) {
                    e = ego4[(size_t)row * 32 + c4];
                    d = side4[(size_t)row * 32 + c4];
                }
                d.x = __bfloat162float(__float2bfloat16(d.x));
                d.y = __bfloat162float(__float2bfloat16(d.y));
                d.z = __bfloat162float(__float2bfloat16(d.z));
                d.w = __bfloat162float(__float2bfloat16(d.w));
                float4 s = make_float4(e.x + d.x, e.y + d.y, e.z + d.z, e.w + d.w);
                float4 p = make_float4(e.x * d.x, e.y * d.y, e.z * d.z, e.w * d.w);

                uint32_t off = swz(r, (uint32_t)c4 * 8);
                float shx = __bfloat162float(__float2bfloat16_rn(s.x));
                float shy = __bfloat162float(__float2bfloat16_rn(s.y));
                float shz = __bfloat162float(__float2bfloat16_rn(s.z));
                float shw = __bfloat162float(__float2bfloat16_rn(s.w));
                uint2 u;
                u.x = pack_bf2(s.x, s.y); u.y = pack_bf2(s.z, s.w);
                *reinterpret_cast<uint2*>(abuf + 0 * A_MAT8 + off) = u;
                u.x = pack_bf2(s.x - shx, s.y - shy); u.y = pack_bf2(s.z - shz, s.w - shw);
                *reinterpret_cast<uint2*>(abuf + 1 * A_MAT8 + off) = u;

                float phx = __bfloat162float(__float2bfloat16_rn(p.x));
                float phy = __bfloat162float(__float2bfloat16_rn(p.y));
                float phz = __bfloat162float(__float2bfloat16_rn(p.z));
                float phw = __bfloat162float(__float2bfloat16_rn(p.w));
                u.x = pack_bf2(p.x, p.y); u.y = pack_bf2(p.z, p.w);
                *reinterpret_cast<uint2*>(abuf + 2 * A_MAT8 + off) = u;
                u.x = pack_bf2(p.x - phx, p.y - phy); u.y = pack_bf2(p.z - phz, p.w - phw);
                *reinterpret_cast<uint2*>(abuf + 3 * A_MAT8 + off) = u;
            }
            __threadfence_block();            // STS visible before full-arrive
            bar_arr(1 + b, THREADS);          // signal buffer full
        }
    } else {
        // ================= CONSUMER (warps 0-7, 256 threads) =================
        int warp_m = (warp >> 2) * 16;        // 0,16
        int warp_n = (warp & 3) * 32;         // 0,32,64,96
        int lrow   = lane & 15;
        int lchunk = (lane >> 4) * 16;

        int col_base = warp_n + (lane & 3) * 2;
        float2 b1v[4], b2v[4];
        #pragma unroll
        for (int nb = 0; nb < 4; nb++) {
            b1v[nb] = *reinterpret_cast<const float2*>(
                          reinterpret_cast<const float*>(smc + SM_B1) + col_base + nb * 8);
            b2v[nb] = *reinterpret_cast<const float2*>(
                          reinterpret_cast<const float*>(smc + SM_B2) + col_base + nb * 8);
        }

        uint32_t arow = (uint32_t)(warp_m + lrow) * ROWB;
        uint32_t xr_a = (uint32_t)((warp_m + lrow) & 7) << 4;
        uint32_t b_addr[2];
        #pragma unroll
        for (int np = 0; np < 2; np++)
            b_addr[np] = sbase + SM_W + (uint32_t)(warp_n + np * 16 + lrow) * ROWB;
        uint32_t xr_b = (uint32_t)((warp_n + lrow) & 7) << 4;

        int k = 0;
        for (int t = blockIdx.x; t < nt; t += gridDim.x, k++) {
            int b = k % NBUF;
            bar_syn(1 + b, THREADS);          // wait buffer full
            uint32_t abase = sbase + SM_A + b * A_BUF + arow;
            int row0 = t * TILE_M;

            float d1[4][4], d2[4][4];
            #pragma unroll
            for (int nb = 0; nb < 4; nb++)
                #pragma unroll
                for (int j = 0; j < 4; j++) { d1[nb][j] = 0.f; d2[nb][j] = 0.f; }

            #pragma unroll
            for (int ks = 0; ks < 8; ks++) {
                uint32_t kA = ((uint32_t)(ks * 32 + lchunk)) ^ xr_a;
                uint32_t kB = ((uint32_t)(ks * 32 + lchunk)) ^ xr_b;

                uint32_t sh[4], sl[4], ph[4], pl[4];
                ldsm_x4(sh, abase + 0 * A_MAT8 + kA);
                ldsm_x4(sl, abase + 1 * A_MAT8 + kA);
                ldsm_x4(ph, abase + 2 * A_MAT8 + kA);
                ldsm_x4(pl, abase + 3 * A_MAT8 + kA);

                uint32_t w1h[2][4], w1l[2][4], w2h[2][4], w2l[2][4];
                #pragma unroll
                for (int np = 0; np < 2; np++) {
                    ldsm_x4(w1h[np], b_addr[np] + 0 * W_MAT + kB);
                    ldsm_x4(w1l[np], b_addr[np] + 1 * W_MAT + kB);
                    ldsm_x4(w2h[np], b_addr[np] + 2 * W_MAT + kB);
                    ldsm_x4(w2l[np], b_addr[np] + 3 * W_MAT + kB);
                }

                #pragma unroll
                for (int np = 0; np < 2; np++) {
                    #pragma unroll
                    for (int j = 0; j < 2; j++) {
                        int nb = np * 2 + j;
                        mma_bf16(d1[nb], sh, w1h[np][j], w1h[np][j + 2]);
                        mma_bf16(d1[nb], sl, w1h[np][j], w1h[np][j + 2]);
                        mma_bf16(d1[nb], sh, w1l[np][j], w1l[np][j + 2]);
                        mma_bf16(d2[nb], ph, w2h[np][j], w2h[np][j + 2]);
                        mma_bf16(d2[nb], pl, w2h[np][j], w2h[np][j + 2]);
                        mma_bf16(d2[nb], ph, w2l[np][j], w2l[np][j + 2]);
                    }
                }
            }
            bar_arr(4 + b, THREADS);          // buffer consumed -> free

            // epilogue (overlaps producer's next fill)
            int r_lo = row0 + warp_m + (lane >> 2);
            int r_hi = r_lo + 8;
            #pragma unroll
            for (int nb = 0; nb < 4; nb++) {
                int col = col_base + nb * 8;
                if (r_lo < n) {
                    float2 o;
                    o.x = lrelu(d1[nb][0] + b1v[nb].x) + lrelu(d2[nb][0] + b2v[nb].x);
                    o.y = lrelu(d1[nb][1] + b1v[nb].y) + lrelu(d2[nb][1] + b2v[nb].y);
                    *reinterpret_cast<float2*>(out + (size_t)r_lo * DIM + col) = o;
                }
                if (r_hi < n) {
                    float2 o;
                    o.x = lrelu(d1[nb][2] + b1v[nb].x) + lrelu(d2[nb][2] + b2v[nb].x);
                    o.y = lrelu(d1[nb][3] + b1v[nb].y) + lrelu(d2[nb][3] + b2v[nb].y);
                    *reinterpret_cast<float2*>(out + (size_t)r_hi * DIM + col) = o;
                }
            }
        }
    }
}

// ---------------------------------------------------------------------------
extern "C" void kernel_launch(void* const* d_in, const int* in_sizes, int n_in,
                              void* d_out, int out_size) {
    const float* ego  = (const float*)d_in[0];
    const float* vals = (const float*)d_in[1];
    const float* W1   = (const float*)d_in[2];
    const float* b1   = (const float*)d_in[3];
    const float* W2   = (const float*)d_in[4];
    const float* b2   = (const float*)d_in[5];
    const int*   rows = (const int*)d_in[6];
    const int*   cols = (const int*)d_in[7];
    float*       out  = (float*)d_out;

    int n = in_sizes[0] / DIM;   // 50000
    int E = in_sizes[1];         // 640000

    cudaFuncSetAttribute(dense_kernel,
                         cudaFuncAttributeMaxDynamicSharedMemorySize, SMEM_BYTES);

    // 1) reset bucket cursors + overflow counter
    void* cnt_ptr = nullptr;
    cudaGetSymbolAddress(&cnt_ptr, g_cnt);
    cudaMemsetAsync(cnt_ptr, 0, (size_t)n * sizeof(int));
    void* ovf_ptr = nullptr;
    cudaGetSymbolAddress(&ovf_ptr, g_ovf_cnt);
    cudaMemsetAsync(ovf_ptr, 0, sizeof(int));

    // 2) bucket fill
    bucket_fill<<<(E + 255) / 256, 256>>>(rows, cols, vals, E);

    // 3) bucket SpMM
    spmm_bucket<<<(n * 32 + 255) / 256, 256>>>(ego, n);

    // 4) overflow fixup
    ovf_fixup<<<64, 256>>>(ego);

    // 5) fused dense (warp-specialized producer/consumer)
    dense_kernel<<<148, THREADS, SMEM_BYTES>>>(ego, W1, b1, W2, b2, out, n);
}